// round 8
// baseline (speedup 1.0000x reference)
#include <cuda_runtime.h>
#include <cstdint>

#define GRID   296
#define BLOCK  256
#define NE     8
#define HDIM   1024

__device__ float g_partials[GRID * 16];
__device__ int   g_ticket = 0;

// Packed fp32x2 FMA (Blackwell): d.lo += a.lo*b.lo ; d.hi += a.hi*b.hi
#define FMA2(d, a, b) asm("fma.rn.f32x2 %0, %1, %2, %0;" : "+l"(d) : "l"(a), "l"(b))

__device__ __forceinline__ void suffix_scan256(int* h, int n)
{
    // inclusive suffix sums, n <= 2048, 256 threads
    for (int off = 1; off < n; off <<= 1) {
        int v[8]; int c = 0;
        for (int i = threadIdx.x; i < n; i += BLOCK) {
            const int add = (i + off < n) ? h[i + off] : 0;
            v[c++] = h[i] + add;
        }
        __syncthreads();
        c = 0;
        for (int i = threadIdx.x; i < n; i += BLOCK) h[i] = v[c++];
        __syncthreads();
    }
}

__global__ void __launch_bounds__(BLOCK, 3)
route_fused(const float* __restrict__ hs, const float* __restrict__ rw,
            float* __restrict__ disp, float* __restrict__ probs,
            float* __restrict__ loss_out, int ntok)
{
    __shared__ __align__(16) float sw[NE * HDIM];
    __shared__ float sW[BLOCK / 32][NE];
    __shared__ float sP[BLOCK / 32][NE];
    __shared__ float red[BLOCK / 32][16];
    __shared__ float sSum[16];
    __shared__ int   hist[2048];          // radix hist; reused as tie buffer
    __shared__ int   s_best, s_tiecnt, s_last;
    __shared__ unsigned s_over;

    // Stage router weights (32KB) into SMEM
    {
        const float4* src = (const float4*)rw;
        float4* dst = (float4*)sw;
        for (int i = threadIdx.x; i < NE * HDIM / 4; i += BLOCK) dst[i] = src[i];
    }
    __syncthreads();

    const int warp = threadIdx.x >> 5;
    const int lane = threadIdx.x & 31;
    const int gwarp = blockIdx.x * (BLOCK / 32) + warp;
    const int nwarps = GRID * (BLOCK / 32);
    const int ngroups = (ntok + 1) >> 1;      // 2 tokens per warp-iteration

    const ulonglong2* __restrict__ hs2 = (const ulonglong2*)hs;  // 256 x 16B per row
    const ulonglong2* __restrict__ w2  = (const ulonglong2*)sw;

    float accW = 0.f;  // lane e<8: running dispatch-weight sum of expert e
    float accP = 0.f;  // lane e<8: running prob sum of expert e

    for (int g = gwarp; g < ngroups; g += nwarps) {
        const int t0 = g << 1;
        const int tcount = (t0 + 2 <= ntok) ? 2 : (ntok - t0);

        unsigned long long acc[2][NE];    // 32 regs
        #pragma unroll
        for (int t = 0; t < 2; t++)
            #pragma unroll
            for (int e = 0; e < NE; e++) acc[t][e] = 0ull;

        const ulonglong2* __restrict__ h0 = hs2 + (size_t)t0 * (HDIM / 4);

        if (tcount == 2) {
            #pragma unroll
            for (int c = 0; c < HDIM / 128; c++) {
                const int off = c * 32 + lane;
                ulonglong2 h[2];
                #pragma unroll
                for (int t = 0; t < 2; t++) h[t] = h0[t * (HDIM / 4) + off];
                #pragma unroll
                for (int e = 0; e < NE; e++) {
                    const ulonglong2 w = w2[e * (HDIM / 4) + off];
                    #pragma unroll
                    for (int t = 0; t < 2; t++) {
                        FMA2(acc[t][e], h[t].x, w.x);
                        FMA2(acc[t][e], h[t].y, w.y);
                    }
                }
            }
        } else {
            for (int c = 0; c < HDIM / 128; c++) {
                const int off = c * 32 + lane;
                for (int t = 0; t < tcount; t++) {
                    const ulonglong2 h = h0[t * (HDIM / 4) + off];
                    #pragma unroll
                    for (int e = 0; e < NE; e++) {
                        const ulonglong2 w = w2[e * (HDIM / 4) + off];
                        FMA2(acc[t][e], h.x, w.x);
                        FMA2(acc[t][e], h.y, w.y);
                    }
                }
            }
        }

        // per-token epilogue — arithmetic bit-identical to the round-2/7 passing kernels
        #pragma unroll
        for (int t = 0; t < 2; t++) {
            if (t >= tcount) break;
            float l[NE];
            #pragma unroll
            for (int e = 0; e < NE; e++) {
                const unsigned long long a = acc[t][e];
                l[e] = __uint_as_float((unsigned)a) + __uint_as_float((unsigned)(a >> 32));
            }
            // Butterfly allreduce across 32 lanes -> ALL lanes hold bit-identical l[0..7]
            #pragma unroll
            for (int s = 16; s > 0; s >>= 1)
                #pragma unroll
                for (int e = 0; e < NE; e++)
                    l[e] += __shfl_xor_sync(0xffffffffu, l[e], s);

            // softmax (TEMPERATURE = 1). mx is bit-identical on every lane, so
            // lane L computes expf for expert L&7 once; the width-8 shfl gather
            // reconstructs ex[0..7] with exactly the same bits and sum order.
            float mx = l[0];
            #pragma unroll
            for (int e = 1; e < NE; e++) mx = fmaxf(mx, l[e]);
            const float ex_own = expf(l[lane & 7] - mx);
            float ex[NE], sum = 0.f;
            #pragma unroll
            for (int e = 0; e < NE; e++) {
                ex[e] = __shfl_sync(0xffffffffu, ex_own, e, 8);
                sum += ex[e];
            }
            const float inv = 1.f / sum;
            float p[NE];
            #pragma unroll
            for (int e = 0; e < NE; e++) p[e] = ex[e] * inv;

            // top-2 (lowest index wins ties), renormalize
            int i1 = 0;
            #pragma unroll
            for (int e = 1; e < NE; e++) if (p[e] > p[i1]) i1 = e;
            int i2 = -1;
            #pragma unroll
            for (int e = 0; e < NE; e++)
                if (e != i1 && (i2 < 0 || p[e] > p[i2])) i2 = e;
            const float dsum = p[i1] + p[i2];
            const float d1 = p[i1] / dsum;
            const float d2 = p[i2] / dsum;

            if (lane < NE) {
                const size_t o = (size_t)(t0 + t) * NE + lane;
                probs[o] = p[lane];
                const float dm = (lane == i1) ? d1 : (lane == i2) ? d2 : 0.f;
                disp[o] = dm;
                accP += p[lane];
                accW += dm;
            }
        }
    }

    if (lane < NE) { sW[warp][lane] = accW; sP[warp][lane] = accP; }
    __syncthreads();
    if (threadIdx.x < 16) {
        const int e = threadIdx.x & 7;
        float s = 0.f;
        if (threadIdx.x < 8) {
            #pragma unroll
            for (int w = 0; w < BLOCK / 32; w++) s += sW[w][e];
        } else {
            #pragma unroll
            for (int w = 0; w < BLOCK / 32; w++) s += sP[w][e];
        }
        g_partials[blockIdx.x * 16 + threadIdx.x] = s;
    }
    __syncthreads();

    // ---- last-block election ----
    if (threadIdx.x == 0) {
        __threadfence();
        const int old = atomicAdd(&g_ticket, 1);
        s_last = (old == GRID - 1);
        if (s_last) g_ticket = 0;   // reset for next launch / replay
    }
    __syncthreads();
    if (!s_last) return;

    // =================== finalize (last block only, 256 threads) ===================
    const int tid = threadIdx.x;
    {
        float s = 0.f;
        for (int i = tid; i < GRID * 16; i += BLOCK) s += g_partials[i];   // col = i & 15
        s += __shfl_xor_sync(0xffffffffu, s, 16);   // lanes L and L+16 share a column
        if (lane < 16) red[warp][lane] = s;
    }
    __syncthreads();
    if (tid < 16) {
        float s = 0.f;
        #pragma unroll
        for (int w = 0; w < BLOCK / 32; w++) s += red[w][tid];
        sSum[tid] = s;
    }
    __syncthreads();

    const int cap = (int)(1.25 * (double)ntok / (double)NE);  // 5120 for N=32768

    if (tid == 0) {
        float l = 0.f;
        for (int e = 0; e < NE; e++) l += sSum[e] * sSum[8 + e];
        loss_out[0] = 0.01f * (l / (float)ntok);
        unsigned m = 0;
        for (int e = 0; e < NE; e++)
            if (sSum[e] > (float)cap) m |= 1u << e;
        s_over = m;
    }
    __syncthreads();
    const unsigned over = s_over;
    if (!over) return;  // fast path: statistically always taken for this data

    // Exact radix-select per over-capacity expert (values in (0,1]; positive
    // float bit patterns are order-monotonic). Levels: bits>>20 | (bits>>9)&0x7FF | bits&0x1FF.
    for (int e = 0; e < NE; e++) {
        if (!((over >> e) & 1u)) continue;

        // level 1: bin = bits >> 20  (<= 0x3F8 for v <= 1.0)
        for (int i = tid; i < 2048; i += BLOCK) hist[i] = 0;
        __syncthreads();
        for (int t = tid; t < ntok; t += BLOCK) {
            const float v = disp[(size_t)t * NE + e];
            if (v > 0.f) atomicAdd(&hist[__float_as_uint(v) >> 20], 1);
        }
        __syncthreads();
        suffix_scan256(hist, 2048);
        if (tid == 0) s_best = -1;
        __syncthreads();
        for (int i = tid; i < 2048; i += BLOCK)
            if (hist[i] >= cap) atomicMax(&s_best, i);
        __syncthreads();
        const int b1 = s_best;
        if (b1 < 0) { __syncthreads(); continue; }
        const int A1 = (b1 + 1 < 2048) ? hist[b1 + 1] : 0;
        const int cap2 = cap - A1;
        __syncthreads();

        // level 2: among bits>>20 == b1: bin = (bits >> 9) & 0x7FF
        for (int i = tid; i < 2048; i += BLOCK) hist[i] = 0;
        __syncthreads();
        for (int t = tid; t < ntok; t += BLOCK) {
            const float v = disp[(size_t)t * NE + e];
            if (v > 0.f) {
                const unsigned b = __float_as_uint(v);
                if ((int)(b >> 20) == b1) atomicAdd(&hist[(b >> 9) & 0x7FF], 1);
            }
        }
        __syncthreads();
        suffix_scan256(hist, 2048);
        if (tid == 0) s_best = -1;
        __syncthreads();
        for (int i = tid; i < 2048; i += BLOCK)
            if (hist[i] >= cap2) atomicMax(&s_best, i);
        __syncthreads();
        const int b2 = s_best;
        const int A2 = (b2 + 1 < 2048) ? hist[b2 + 1] : 0;
        const int cap3 = cap2 - A2;
        const unsigned key = ((unsigned)b1 << 11) | (unsigned)b2;   // == bits >> 9
        __syncthreads();

        // level 3: among bits>>9 == key: bin = bits & 0x1FF
        for (int i = tid; i < 512; i += BLOCK) hist[i] = 0;
        __syncthreads();
        for (int t = tid; t < ntok; t += BLOCK) {
            const float v = disp[(size_t)t * NE + e];
            if (v > 0.f) {
                const unsigned b = __float_as_uint(v);
                if ((b >> 9) == key) atomicAdd(&hist[b & 0x1FF], 1);
            }
        }
        __syncthreads();
        suffix_scan256(hist, 512);
        if (tid == 0) s_best = -1;
        __syncthreads();
        for (int i = tid; i < 512; i += BLOCK)
            if (hist[i] >= cap3) atomicMax(&s_best, i);
        __syncthreads();
        const int b3 = s_best;
        const int A3 = (b3 + 1 < 512) ? hist[b3 + 1] : 0;
        const int keep_eq = cap3 - A3;            // ==threshold entries that survive
        const unsigned thr = (key << 9) | (unsigned)b3;
        __syncthreads();

        // apply: zero below threshold; collect exact ties (reuse hist as buffer)
        int* s_ties = hist;
        if (tid == 0) s_tiecnt = 0;
        __syncthreads();
        for (int t = tid; t < ntok; t += BLOCK) {
            const size_t o = (size_t)t * NE + e;
            const float v = disp[o];
            if (v > 0.f) {
                const unsigned b = __float_as_uint(v);
                if (b < thr) {
                    disp[o] = 0.f;
                } else if (b == thr) {
                    const int p = atomicAdd(&s_tiecnt, 1);
                    if (p < 2048) s_ties[p] = t;
                }
            }
        }
        __syncthreads();
        const int tc = (s_tiecnt < 2048) ? s_tiecnt : 2048;
        if (s_tiecnt > keep_eq) {
            // keep the keep_eq ties with smallest token index (jax top_k order)
            for (int i = tid; i < tc; i += BLOCK) {
                const int ti = s_ties[i];
                int rank = 0;
                for (int j = 0; j < tc; j++) rank += (s_ties[j] < ti);
                if (rank >= keep_eq) disp[(size_t)ti * NE + e] = 0.f;
            }
        }
        __syncthreads();
    }
}

extern "C" void kernel_launch(void* const* d_in, const int* in_sizes, int n_in,
                              void* d_out, int out_size)
{
    const float* hs = (const float*)d_in[0];
    const float* rw = (const float*)d_in[1];
    int hsize = in_sizes[0];
    if (n_in >= 2 && in_sizes[0] < in_sizes[1]) {  // defensive: pick the big tensor as hidden
        hs = (const float*)d_in[1];
        rw = (const float*)d_in[0];
        hsize = in_sizes[1];
    }
    const int ntok = hsize / HDIM;

    float* out   = (float*)d_out;
    float* disp  = out;                          // [N, E]
    float* loss  = out + (size_t)ntok * NE;      // scalar
    float* probs = loss + 1;                     // [N, E]

    route_fused<<<GRID, BLOCK>>>(hs, rw, disp, probs, loss, ntok);
}

// round 9
// speedup vs baseline: 1.1522x; 1.1522x over previous
#include <cuda_runtime.h>
#include <cstdint>

#define GRID   444
#define BLOCK  256
#define NE     8
#define HDIM   1024

__device__ float g_partials[GRID * 16];
__device__ int   g_ticket = 0;

// Packed fp32x2 FMA (Blackwell): d.lo += a.lo*b.lo ; d.hi += a.hi*b.hi
#define FMA2(d, a, b) asm("fma.rn.f32x2 %0, %1, %2, %0;" : "+l"(d) : "l"(a), "l"(b))

__device__ __forceinline__ void suffix_scan256(int* h, int n)
{
    // inclusive suffix sums, n <= 2048, 256 threads
    for (int off = 1; off < n; off <<= 1) {
        int v[8]; int c = 0;
        for (int i = threadIdx.x; i < n; i += BLOCK) {
            const int add = (i + off < n) ? h[i + off] : 0;
            v[c++] = h[i] + add;
        }
        __syncthreads();
        c = 0;
        for (int i = threadIdx.x; i < n; i += BLOCK) h[i] = v[c++];
        __syncthreads();
    }
}

__global__ void __launch_bounds__(BLOCK, 3)
route_fused(const float* __restrict__ hs, const float* __restrict__ rw,
            float* __restrict__ disp, float* __restrict__ probs,
            float* __restrict__ loss_out, int ntok)
{
    __shared__ __align__(16) float sw[NE * HDIM];   // weights; reused as hist/ties in finalize
    __shared__ float sW[BLOCK / 32][NE];
    __shared__ float sP[BLOCK / 32][NE];
    __shared__ float red[BLOCK / 32][16];
    __shared__ float sSum[16];
    __shared__ int   s_best, s_tiecnt, s_last;
    __shared__ unsigned s_over;

    // Stage router weights (32KB) into SMEM
    {
        const float4* src = (const float4*)rw;
        float4* dst = (float4*)sw;
        for (int i = threadIdx.x; i < NE * HDIM / 4; i += BLOCK) dst[i] = src[i];
    }
    __syncthreads();

    const int warp = threadIdx.x >> 5;
    const int lane = threadIdx.x & 31;
    const int gwarp = blockIdx.x * (BLOCK / 32) + warp;
    const int nwarps = GRID * (BLOCK / 32);
    const int ngroups = (ntok + 1) >> 1;      // 2 tokens per warp-iteration

    const ulonglong2* __restrict__ hs2 = (const ulonglong2*)hs;  // 256 x 16B per row
    const ulonglong2* __restrict__ w2  = (const ulonglong2*)sw;

    float accW = 0.f;  // lane e<8: running dispatch-weight sum of expert e
    float accP = 0.f;  // lane e<8: running prob sum of expert e

    for (int g = gwarp; g < ngroups; g += nwarps) {
        const int t0 = g << 1;
        const int tcount = (t0 + 2 <= ntok) ? 2 : (ntok - t0);

        unsigned long long acc[2][NE];    // 32 regs
        #pragma unroll
        for (int t = 0; t < 2; t++)
            #pragma unroll
            for (int e = 0; e < NE; e++) acc[t][e] = 0ull;

        const ulonglong2* __restrict__ h0 = hs2 + (size_t)t0 * (HDIM / 4);

        if (tcount == 2) {
            // double-buffered h: chunk c+1's global loads issue before chunk c's FMAs
            ulonglong2 hb[2][2];
            hb[0][0] = h0[lane];
            hb[0][1] = h0[(HDIM / 4) + lane];
            #pragma unroll
            for (int c = 0; c < HDIM / 128; c++) {
                const int cur = c & 1, nxt = cur ^ 1;
                if (c + 1 < HDIM / 128) {
                    const int off = (c + 1) * 32 + lane;
                    hb[nxt][0] = h0[off];
                    hb[nxt][1] = h0[(HDIM / 4) + off];
                }
                const int off = c * 32 + lane;
                #pragma unroll
                for (int e = 0; e < NE; e++) {
                    const ulonglong2 w = w2[e * (HDIM / 4) + off];
                    #pragma unroll
                    for (int t = 0; t < 2; t++) {
                        FMA2(acc[t][e], hb[cur][t].x, w.x);
                        FMA2(acc[t][e], hb[cur][t].y, w.y);
                    }
                }
            }
        } else {
            for (int c = 0; c < HDIM / 128; c++) {
                const int off = c * 32 + lane;
                for (int t = 0; t < tcount; t++) {
                    const ulonglong2 h = h0[t * (HDIM / 4) + off];
                    #pragma unroll
                    for (int e = 0; e < NE; e++) {
                        const ulonglong2 w = w2[e * (HDIM / 4) + off];
                        FMA2(acc[t][e], h.x, w.x);
                        FMA2(acc[t][e], h.y, w.y);
                    }
                }
            }
        }

        // per-token epilogue — arithmetic bit-identical to the round-2/7/8 passing kernels
        #pragma unroll
        for (int t = 0; t < 2; t++) {
            if (t >= tcount) break;
            float l[NE];
            #pragma unroll
            for (int e = 0; e < NE; e++) {
                const unsigned long long a = acc[t][e];
                l[e] = __uint_as_float((unsigned)a) + __uint_as_float((unsigned)(a >> 32));
            }
            // Butterfly allreduce across 32 lanes -> ALL lanes hold bit-identical l[0..7]
            #pragma unroll
            for (int s = 16; s > 0; s >>= 1)
                #pragma unroll
                for (int e = 0; e < NE; e++)
                    l[e] += __shfl_xor_sync(0xffffffffu, l[e], s);

            // softmax (TEMPERATURE = 1); lane L computes expf for expert L&7 once,
            // width-8 shfl gather reconstructs ex[0..7] bit-exactly, same sum order.
            float mx = l[0];
            #pragma unroll
            for (int e = 1; e < NE; e++) mx = fmaxf(mx, l[e]);
            const float ex_own = expf(l[lane & 7] - mx);
            float ex[NE], sum = 0.f;
            #pragma unroll
            for (int e = 0; e < NE; e++) {
                ex[e] = __shfl_sync(0xffffffffu, ex_own, e, 8);
                sum += ex[e];
            }
            const float inv = 1.f / sum;
            float p[NE];
            #pragma unroll
            for (int e = 0; e < NE; e++) p[e] = ex[e] * inv;

            // top-2 (lowest index wins ties), renormalize
            int i1 = 0;
            #pragma unroll
            for (int e = 1; e < NE; e++) if (p[e] > p[i1]) i1 = e;
            int i2 = -1;
            #pragma unroll
            for (int e = 0; e < NE; e++)
                if (e != i1 && (i2 < 0 || p[e] > p[i2])) i2 = e;
            const float dsum = p[i1] + p[i2];
            const float d1 = p[i1] / dsum;
            const float d2 = p[i2] / dsum;

            if (lane < NE) {
                const size_t o = (size_t)(t0 + t) * NE + lane;
                probs[o] = p[lane];
                const float dm = (lane == i1) ? d1 : (lane == i2) ? d2 : 0.f;
                disp[o] = dm;
                accP += p[lane];
                accW += dm;
            }
        }
    }

    if (lane < NE) { sW[warp][lane] = accW; sP[warp][lane] = accP; }
    __syncthreads();
    if (threadIdx.x < 16) {
        const int e = threadIdx.x & 7;
        float s = 0.f;
        if (threadIdx.x < 8) {
            #pragma unroll
            for (int w = 0; w < BLOCK / 32; w++) s += sW[w][e];
        } else {
            #pragma unroll
            for (int w = 0; w < BLOCK / 32; w++) s += sP[w][e];
        }
        g_partials[blockIdx.x * 16 + threadIdx.x] = s;
    }
    __syncthreads();

    // ---- last-block election ----
    if (threadIdx.x == 0) {
        __threadfence();
        const int old = atomicAdd(&g_ticket, 1);
        s_last = (old == GRID - 1);
        if (s_last) g_ticket = 0;   // reset for next launch / replay
    }
    __syncthreads();
    if (!s_last) return;

    // =================== finalize (last block only, 256 threads) ===================
    const int tid = threadIdx.x;
    int* hist = (int*)sw;            // weights no longer needed: reuse as hist/ties
    {
        float s = 0.f;
        for (int i = tid; i < GRID * 16; i += BLOCK) s += g_partials[i];   // col = i & 15
        s += __shfl_xor_sync(0xffffffffu, s, 16);   // lanes L and L+16 share a column
        if (lane < 16) red[warp][lane] = s;
    }
    __syncthreads();
    if (tid < 16) {
        float s = 0.f;
        #pragma unroll
        for (int w = 0; w < BLOCK / 32; w++) s += red[w][tid];
        sSum[tid] = s;
    }
    __syncthreads();

    const int cap = (int)(1.25 * (double)ntok / (double)NE);  // 5120 for N=32768

    if (tid == 0) {
        float l = 0.f;
        for (int e = 0; e < NE; e++) l += sSum[e] * sSum[8 + e];
        loss_out[0] = 0.01f * (l / (float)ntok);
        unsigned m = 0;
        for (int e = 0; e < NE; e++)
            if (sSum[e] > (float)cap) m |= 1u << e;
        s_over = m;
    }
    __syncthreads();
    const unsigned over = s_over;
    if (!over) return;  // fast path: statistically always taken for this data

    // Exact radix-select per over-capacity expert (values in (0,1]; positive
    // float bit patterns are order-monotonic). Levels: bits>>20 | (bits>>9)&0x7FF | bits&0x1FF.
    for (int e = 0; e < NE; e++) {
        if (!((over >> e) & 1u)) continue;

        // level 1: bin = bits >> 20  (<= 0x3F8 for v <= 1.0)
        for (int i = tid; i < 2048; i += BLOCK) hist[i] = 0;
        __syncthreads();
        for (int t = tid; t < ntok; t += BLOCK) {
            const float v = disp[(size_t)t * NE + e];
            if (v > 0.f) atomicAdd(&hist[__float_as_uint(v) >> 20], 1);
        }
        __syncthreads();
        suffix_scan256(hist, 2048);
        if (tid == 0) s_best = -1;
        __syncthreads();
        for (int i = tid; i < 2048; i += BLOCK)
            if (hist[i] >= cap) atomicMax(&s_best, i);
        __syncthreads();
        const int b1 = s_best;
        if (b1 < 0) { __syncthreads(); continue; }
        const int A1 = (b1 + 1 < 2048) ? hist[b1 + 1] : 0;
        const int cap2 = cap - A1;
        __syncthreads();

        // level 2: among bits>>20 == b1: bin = (bits >> 9) & 0x7FF
        for (int i = tid; i < 2048; i += BLOCK) hist[i] = 0;
        __syncthreads();
        for (int t = tid; t < ntok; t += BLOCK) {
            const float v = disp[(size_t)t * NE + e];
            if (v > 0.f) {
                const unsigned b = __float_as_uint(v);
                if ((int)(b >> 20) == b1) atomicAdd(&hist[(b >> 9) & 0x7FF], 1);
            }
        }
        __syncthreads();
        suffix_scan256(hist, 2048);
        if (tid == 0) s_best = -1;
        __syncthreads();
        for (int i = tid; i < 2048; i += BLOCK)
            if (hist[i] >= cap2) atomicMax(&s_best, i);
        __syncthreads();
        const int b2 = s_best;
        const int A2 = (b2 + 1 < 2048) ? hist[b2 + 1] : 0;
        const int cap3 = cap2 - A2;
        const unsigned key = ((unsigned)b1 << 11) | (unsigned)b2;   // == bits >> 9
        __syncthreads();

        // level 3: among bits>>9 == key: bin = bits & 0x1FF
        for (int i = tid; i < 512; i += BLOCK) hist[i] = 0;
        __syncthreads();
        for (int t = tid; t < ntok; t += BLOCK) {
            const float v = disp[(size_t)t * NE + e];
            if (v > 0.f) {
                const unsigned b = __float_as_uint(v);
                if ((b >> 9) == key) atomicAdd(&hist[b & 0x1FF], 1);
            }
        }
        __syncthreads();
        suffix_scan256(hist, 512);
        if (tid == 0) s_best = -1;
        __syncthreads();
        for (int i = tid; i < 512; i += BLOCK)
            if (hist[i] >= cap3) atomicMax(&s_best, i);
        __syncthreads();
        const int b3 = s_best;
        const int A3 = (b3 + 1 < 512) ? hist[b3 + 1] : 0;
        const int keep_eq = cap3 - A3;            // ==threshold entries that survive
        const unsigned thr = (key << 9) | (unsigned)b3;
        __syncthreads();

        // apply: zero below threshold; collect exact ties (reuse hist as buffer)
        int* s_ties = hist;
        if (tid == 0) s_tiecnt = 0;
        __syncthreads();
        for (int t = tid; t < ntok; t += BLOCK) {
            const size_t o = (size_t)t * NE + e;
            const float v = disp[o];
            if (v > 0.f) {
                const unsigned b = __float_as_uint(v);
                if (b < thr) {
                    disp[o] = 0.f;
                } else if (b == thr) {
                    const int p = atomicAdd(&s_tiecnt, 1);
                    if (p < 2048) s_ties[p] = t;
                }
            }
        }
        __syncthreads();
        const int tc = (s_tiecnt < 2048) ? s_tiecnt : 2048;
        if (s_tiecnt > keep_eq) {
            // keep the keep_eq ties with smallest token index (jax top_k order)
            for (int i = tid; i < tc; i += BLOCK) {
                const int ti = s_ties[i];
                int rank = 0;
                for (int j = 0; j < tc; j++) rank += (s_ties[j] < ti);
                if (rank >= keep_eq) disp[(size_t)ti * NE + e] = 0.f;
            }
        }
        __syncthreads();
    }
}

extern "C" void kernel_launch(void* const* d_in, const int* in_sizes, int n_in,
                              void* d_out, int out_size)
{
    const float* hs = (const float*)d_in[0];
    const float* rw = (const float*)d_in[1];
    int hsize = in_sizes[0];
    if (n_in >= 2 && in_sizes[0] < in_sizes[1]) {  // defensive: pick the big tensor as hidden
        hs = (const float*)d_in[1];
        rw = (const float*)d_in[0];
        hsize = in_sizes[1];
    }
    const int ntok = hsize / HDIM;

    float* out   = (float*)d_out;
    float* disp  = out;                          // [N, E]
    float* loss  = out + (size_t)ntok * NE;      // scalar
    float* probs = loss + 1;                     // [N, E]

    route_fused<<<GRID, BLOCK>>>(hs, rw, disp, probs, loss, ntok);
}